// round 6
// baseline (speedup 1.0000x reference)
#include <cuda_runtime.h>
#include <math.h>

// Problem constants (fixed by reference setup_inputs)
#define H        512
#define BATCH    128
#define ENC_LEN  100
#define TSTEPS   1024
#define STEP_ELEMS (BATCH * H)   // 65536 floats per timestep

// Persistent-kernel geometry
#define GRID     128             // 32 j-chunks x 4 batch-chunks (<= 148 SMs, all co-resident)
#define NTHREADS 256
#define JC       16              // h-dims per j-chunk
#define BC       32              // batch rows per batch-chunk
#define NROWS    64              // 4 gates * JC rows of combined weights per CTA
#define WPAD     524             // row stride (floats): 524%32=12 -> conflict-free LDS.128
#define PPAD     20              // partial-exchange stride (floats), float4-aligned, conflict-free

// SMEM layout (floats)
#define W_OFF    0
#define H_OFF    (NROWS * WPAD)                  // 33536
#define B_OFF    (H_OFF + BC * H)                // +16384 = 49920
#define P_OFF    (B_OFF + NROWS)                 // +64    = 49984
#define SMEM_FLOATS (P_OFF + 128 * PPAD)         // +2560  = 52544
#define SMEM_BYTES  (SMEM_FLOATS * 4)            // 210176 B

__device__ unsigned long long g_count;

__global__ void init_kernel() { g_count = 0ULL; }

__device__ __forceinline__ float sigm(float x) { return 1.0f / (1.0f + expf(-x)); }

// ---------------------------------------------------------------------------
// Step 0: x = 0, h = h0 = encoder_outputs[0, b, ENC_LEN-1, :]
//   gh = h0 @ W_hh^T + b_hh ;  gi = b_ih
//   r = sig(gi_r + gh_r); z = sig(gi_z + gh_z); n = tanh(gi_n + r*gh_n)
//   out[0][b] = (1-z)*n + z*h0
// One CTA per batch row; warp-per-output-row cooperative dot products.
// ---------------------------------------------------------------------------
__global__ void gru_step0(const float* __restrict__ enc,
                          const float* __restrict__ W_hh,
                          const float* __restrict__ b_ih,
                          const float* __restrict__ b_hh,
                          float* __restrict__ out)
{
    __shared__ float h0s[H];
    __shared__ float gh[3 * H];

    const int b   = blockIdx.x;
    const int tid = threadIdx.x;

    const float* src = enc + ((size_t)b * ENC_LEN + (ENC_LEN - 1)) * H;
    for (int i = tid; i < H; i += NTHREADS) h0s[i] = src[i];
    __syncthreads();

    const int warp = tid >> 5, lane = tid & 31;
    const float4* h4 = (const float4*)h0s;
    for (int row = warp; row < 3 * H; row += (NTHREADS / 32)) {
        const float4* wr = (const float4*)(W_hh + (size_t)row * H);
        float s = 0.0f;
        #pragma unroll 4
        for (int i = lane; i < H / 4; i += 32) {
            float4 w = wr[i]; float4 hv = h4[i];
            s = fmaf(w.x, hv.x, s); s = fmaf(w.y, hv.y, s);
            s = fmaf(w.z, hv.z, s); s = fmaf(w.w, hv.w, s);
        }
        #pragma unroll
        for (int o = 16; o > 0; o >>= 1) s += __shfl_xor_sync(0xffffffffu, s, o);
        if (lane == 0) gh[row] = s;
    }
    __syncthreads();

    for (int j = tid; j < H; j += NTHREADS) {
        float r = sigm(b_ih[j]         + gh[j]         + b_hh[j]);
        float z = sigm(b_ih[H + j]     + gh[H + j]     + b_hh[H + j]);
        float n = tanhf(b_ih[2*H + j]  + r * (gh[2*H + j] + b_hh[2*H + j]));
        float ho = h0s[j];
        out[(size_t)b * H + j] = n + z * (ho - n);   // (1-z)*n + z*h
    }
}

// ---------------------------------------------------------------------------
// Persistent kernel: steps 1..1023. For t>=1, x == h, so gates read combined
// weights kept stationary in SMEM:
//   gate 0 (r): W_ih[0:H]   + W_hh[0:H]      bias b_ih+b_hh
//   gate 1 (z): W_ih[H:2H]  + W_hh[H:2H]     bias b_ih+b_hh
//   gate 2 (a): W_ih[2H:3H]                  bias b_ih
//   gate 3 (g): W_hh[2H:3H]                  bias b_hh
//   h' = (1-z)*tanh(a + sig(r)*g) + z*h,   z := sig(zpre), r := sig(rpre)
// CTA = (jc, bc): 16 h-dims x 32 batch rows. 256 threads split K in half
// (kh = tid>>7); each thread owns a 4-gate x 4-batch register tile over one j.
// One software grid barrier per step (monotonic counter).
// ---------------------------------------------------------------------------
__global__ void __launch_bounds__(NTHREADS, 1)
gru_persist(const float* __restrict__ W_ih,
            const float* __restrict__ W_hh,
            const float* __restrict__ b_ih,
            const float* __restrict__ b_hh,
            float* __restrict__ out)
{
    extern __shared__ float sm[];
    float* w_s    = sm + W_OFF;   // [NROWS][WPAD]
    float* h_s    = sm + H_OFF;   // [BC][H]
    float* bias_s = sm + B_OFF;   // [NROWS]
    float* part_s = sm + P_OFF;   // [128][PPAD]

    const int tid = threadIdx.x;
    const int cta = blockIdx.x;
    const int jc  = cta & 31;     // 32 j-chunks
    const int bc  = cta >> 5;     // 4 batch-chunks

    // ---- Prologue: build combined weight tile in SMEM (coalesced gmem reads)
    for (int idx = tid; idx < NROWS * H; idx += NTHREADS) {
        int rl = idx >> 9, k = idx & (H - 1);
        int g = rl >> 4, j = rl & 15;
        int grow = jc * JC + j;
        float v;
        if (g == 0)      v = W_ih[(size_t)grow * H + k]           + W_hh[(size_t)grow * H + k];
        else if (g == 1) v = W_ih[(size_t)(H + grow) * H + k]     + W_hh[(size_t)(H + grow) * H + k];
        else if (g == 2) v = W_ih[(size_t)(2*H + grow) * H + k];
        else             v = W_hh[(size_t)(2*H + grow) * H + k];
        w_s[rl * WPAD + k] = v;
    }
    if (tid < NROWS) {
        int g = tid >> 4, j = tid & 15;
        int grow = jc * JC + j;
        float v;
        if (g == 0)      v = b_ih[grow]        + b_hh[grow];
        else if (g == 1) v = b_ih[H + grow]    + b_hh[H + grow];
        else if (g == 2) v = b_ih[2*H + grow];
        else             v = b_hh[2*H + grow];
        bias_s[tid] = v;
    }
    __syncthreads();

    const int lj = tid & 15;          // j within chunk
    const int bg = (tid >> 4) & 7;    // batch group (4 rows each)
    const int kh = tid >> 7;          // k half: 0 -> [0,256), 1 -> [256,512)

    // Operand pointers are invariant across timesteps — hoist.
    const float4* W0 = (const float4*)(w_s + (0*JC + lj) * WPAD + kh * (H/2));
    const float4* W1 = (const float4*)(w_s + (1*JC + lj) * WPAD + kh * (H/2));
    const float4* W2 = (const float4*)(w_s + (2*JC + lj) * WPAD + kh * (H/2));
    const float4* W3 = (const float4*)(w_s + (3*JC + lj) * WPAD + kh * (H/2));
    const float4* Hv0 = (const float4*)(h_s + (bg*4 + 0) * H + kh * (H/2));
    const float4* Hv1 = (const float4*)(h_s + (bg*4 + 1) * H + kh * (H/2));
    const float4* Hv2 = (const float4*)(h_s + (bg*4 + 2) * H + kh * (H/2));
    const float4* Hv3 = (const float4*)(h_s + (bg*4 + 3) * H + kh * (H/2));

    const float bias0 = bias_s[0*JC + lj];
    const float bias1 = bias_s[1*JC + lj];
    const float bias2 = bias_s[2*JC + lj];
    const float bias3 = bias_s[3*JC + lj];

    for (int t = 1; t < TSTEPS; ++t) {
        // ---- load h tile (this CTA's 32 batch rows of out[t-1]) into SMEM
        const float4* src = (const float4*)(out + (size_t)(t - 1) * STEP_ELEMS
                                            + (size_t)bc * BC * H);
        float4* hdst = (float4*)h_s;
        #pragma unroll
        for (int i = 0; i < (BC * H / 4) / NTHREADS; ++i)
            hdst[tid + i * NTHREADS] = __ldcg(src + tid + i * NTHREADS);
        __syncthreads();

        // ---- 16 dot-products (4 gates x 4 batches) over this thread's K-half
        float a0[4], a1[4], a2[4], a3[4];
        #pragma unroll
        for (int i = 0; i < 4; ++i) {
            a0[i] = (kh == 0) ? bias0 : 0.0f;
            a1[i] = (kh == 0) ? bias1 : 0.0f;
            a2[i] = (kh == 0) ? bias2 : 0.0f;
            a3[i] = (kh == 0) ? bias3 : 0.0f;
        }

        #pragma unroll 8
        for (int kk = 0; kk < (H/2) / 4; ++kk) {
            float4 w0 = W0[kk], w1 = W1[kk], w2 = W2[kk], w3 = W3[kk];
            float4 x0 = Hv0[kk], x1 = Hv1[kk], x2 = Hv2[kk], x3 = Hv3[kk];
            #define ACC(av, wv, xv) \
                av = fmaf(wv.x, xv.x, av); av = fmaf(wv.y, xv.y, av); \
                av = fmaf(wv.z, xv.z, av); av = fmaf(wv.w, xv.w, av);
            ACC(a0[0], w0, x0) ACC(a0[1], w0, x1) ACC(a0[2], w0, x2) ACC(a0[3], w0, x3)
            ACC(a1[0], w1, x0) ACC(a1[1], w1, x1) ACC(a1[2], w1, x2) ACC(a1[3], w1, x3)
            ACC(a2[0], w2, x0) ACC(a2[1], w2, x1) ACC(a2[2], w2, x2) ACC(a2[3], w2, x3)
            ACC(a3[0], w3, x0) ACC(a3[1], w3, x1) ACC(a3[2], w3, x2) ACC(a3[3], w3, x3)
            #undef ACC
        }

        // ---- cross-half reduction via SMEM (kh==1 -> kh==0)
        if (kh == 1) {
            float4* p = (float4*)(part_s + (tid & 127) * PPAD);
            p[0] = make_float4(a0[0], a0[1], a0[2], a0[3]);
            p[1] = make_float4(a1[0], a1[1], a1[2], a1[3]);
            p[2] = make_float4(a2[0], a2[1], a2[2], a2[3]);
            p[3] = make_float4(a3[0], a3[1], a3[2], a3[3]);
        }
        __syncthreads();

        if (kh == 0) {
            const float4* p = (const float4*)(part_s + tid * PPAD);
            float4 q0 = p[0], q1 = p[1], q2 = p[2], q3 = p[3];
            a0[0] += q0.x; a0[1] += q0.y; a0[2] += q0.z; a0[3] += q0.w;
            a1[0] += q1.x; a1[1] += q1.y; a1[2] += q1.z; a1[3] += q1.w;
            a2[0] += q2.x; a2[1] += q2.y; a2[2] += q2.z; a2[3] += q2.w;
            a3[0] += q3.x; a3[1] += q3.y; a3[2] += q3.z; a3[3] += q3.w;

            const int jglob = jc * JC + lj;
            float* dst = out + (size_t)t * STEP_ELEMS + (size_t)(bc * BC + bg * 4) * H + jglob;
            #pragma unroll
            for (int i = 0; i < 4; ++i) {
                float r = sigm(a0[i]);
                float z = sigm(a1[i]);
                float n = tanhf(a2[i] + r * a3[i]);
                float ho = h_s[(bg * 4 + i) * H + jglob];
                dst[(size_t)i * H] = n + z * (ho - n);   // (1-z)*n + z*h
            }
        }

        // ---- grid barrier (skip after final step)
        if (t + 1 < TSTEPS) {
            __threadfence();      // publish out[t] stores gpu-wide
            __syncthreads();
            if (tid == 0) {
                atomicAdd(&g_count, 1ULL);
                unsigned long long target = (unsigned long long)t * (unsigned long long)GRID;
                while (*(volatile unsigned long long*)&g_count < target) { }
            }
            __syncthreads();
        }
    }
}

// ---------------------------------------------------------------------------
// Harness entry
// Inputs (metadata order): encoder_outputs f32[1,128,100,512], W_ih f32[1536,512],
//   W_hh f32[1536,512], b_ih f32[1536], b_hh f32[1536], out_len i32 (unused; fixed 1024)
// Output: f32[1024*128, 1, 512]
// ---------------------------------------------------------------------------
extern "C" void kernel_launch(void* const* d_in, const int* in_sizes, int n_in,
                              void* d_out, int out_size)
{
    const float* enc  = (const float*)d_in[0];
    const float* W_ih = (const float*)d_in[1];
    const float* W_hh = (const float*)d_in[2];
    const float* b_ih = (const float*)d_in[3];
    const float* b_hh = (const float*)d_in[4];
    float* out = (float*)d_out;

    cudaFuncSetAttribute(gru_persist, cudaFuncAttributeMaxDynamicSharedMemorySize, SMEM_BYTES);

    init_kernel<<<1, 1>>>();
    gru_step0<<<BATCH, NTHREADS>>>(enc, W_hh, b_ih, b_hh, out);
    gru_persist<<<GRID, NTHREADS, SMEM_BYTES>>>(W_ih, W_hh, b_ih, b_hh, out);
}

// round 8
// speedup vs baseline: 1.0192x; 1.0192x over previous
#include <cuda_runtime.h>
#include <math.h>

// Problem constants (fixed by reference setup_inputs)
#define H        512
#define BATCH    128
#define ENC_LEN  100
#define TSTEPS   1024
#define STEP_ELEMS (BATCH * H)   // 65536 floats per timestep

// Persistent-kernel geometry
#define GRID     128             // 32 j-chunks x 4 batch-chunks (<= 148 SMs, all co-resident)
#define NTHREADS 256
#define JC       16              // h-dims per j-chunk
#define BC       32              // batch rows per batch-chunk
#define NROWS    64              // 4 gates * JC rows of combined weights per CTA
#define WPAD     524             // row stride (floats): conflict-free LDS.128
#define PPAD     20              // partial-exchange stride (floats), float4-aligned, conflict-free

// SMEM layout (floats)
#define W_OFF    0
#define H_OFF    (NROWS * WPAD)                  // 33536
#define B_OFF    (H_OFF + BC * H)                // +16384 = 49920
#define P_OFF    (B_OFF + NROWS)                 // +64    = 49984
#define SMEM_FLOATS (P_OFF + 128 * PPAD)         // +2560  = 52544
#define SMEM_BYTES  (SMEM_FLOATS * 4)            // 210176 B

typedef unsigned long long u64;

// Packed 2-wide fp32 FMA (Blackwell FFMA2) — only reachable via PTX f32x2.
#define FFMA2(acc, w, x) \
    asm("fma.rn.f32x2 %0, %1, %2, %0;" : "+l"(acc) : "l"(w), "l"(x))

__device__ __forceinline__ float pairsum(u64 v) {
    float lo, hi;
    asm("mov.b64 {%0, %1}, %2;" : "=f"(lo), "=f"(hi) : "l"(v));
    return lo + hi;
}

__device__ unsigned long long g_count;

__global__ void init_kernel() { g_count = 0ULL; }

__device__ __forceinline__ float sigm(float x) { return 1.0f / (1.0f + expf(-x)); }

// ---------------------------------------------------------------------------
// Step 0: x = 0, h = h0 = encoder_outputs[0, b, ENC_LEN-1, :]
// ---------------------------------------------------------------------------
__global__ void gru_step0(const float* __restrict__ enc,
                          const float* __restrict__ W_hh,
                          const float* __restrict__ b_ih,
                          const float* __restrict__ b_hh,
                          float* __restrict__ out)
{
    __shared__ float h0s[H];
    __shared__ float gh[3 * H];

    const int b   = blockIdx.x;
    const int tid = threadIdx.x;

    const float* src = enc + ((size_t)b * ENC_LEN + (ENC_LEN - 1)) * H;
    for (int i = tid; i < H; i += NTHREADS) h0s[i] = src[i];
    __syncthreads();

    const int warp = tid >> 5, lane = tid & 31;
    const float4* h4 = (const float4*)h0s;
    for (int row = warp; row < 3 * H; row += (NTHREADS / 32)) {
        const float4* wr = (const float4*)(W_hh + (size_t)row * H);
        float s = 0.0f;
        #pragma unroll 4
        for (int i = lane; i < H / 4; i += 32) {
            float4 w = wr[i]; float4 hv = h4[i];
            s = fmaf(w.x, hv.x, s); s = fmaf(w.y, hv.y, s);
            s = fmaf(w.z, hv.z, s); s = fmaf(w.w, hv.w, s);
        }
        #pragma unroll
        for (int o = 16; o > 0; o >>= 1) s += __shfl_xor_sync(0xffffffffu, s, o);
        if (lane == 0) gh[row] = s;
    }
    __syncthreads();

    for (int j = tid; j < H; j += NTHREADS) {
        float r = sigm(b_ih[j]         + gh[j]         + b_hh[j]);
        float z = sigm(b_ih[H + j]     + gh[H + j]     + b_hh[H + j]);
        float n = tanhf(b_ih[2*H + j]  + r * (gh[2*H + j] + b_hh[2*H + j]));
        float ho = h0s[j];
        out[(size_t)b * H + j] = n + z * (ho - n);   // (1-z)*n + z*h
    }
}

// ---------------------------------------------------------------------------
// Persistent kernel: steps 1..1023. x == h for t>=1, so gates use combined
// weights stationary in SMEM (4 gates: r, z, a=x-part of n, g=h-part of n).
//   h' = (1-z)*tanh(a + sig(r)*g) + z*h
// CTA = (jc, bc): 16 h-dims x 32 batch rows. 256 threads split K in half;
// each thread: 4-gate x 4-batch tile, accumulated in packed f32x2 pairs
// over adjacent k (FFMA2 — halves FMA-pipe instruction count).
// One software grid barrier per step.
// ---------------------------------------------------------------------------
__global__ void __launch_bounds__(NTHREADS, 1)
gru_persist(const float* __restrict__ W_ih,
            const float* __restrict__ W_hh,
            const float* __restrict__ b_ih,
            const float* __restrict__ b_hh,
            float* __restrict__ out)
{
    extern __shared__ float sm[];
    float* w_s    = sm + W_OFF;   // [NROWS][WPAD]
    float* h_s    = sm + H_OFF;   // [BC][H]
    float* bias_s = sm + B_OFF;   // [NROWS]
    float* part_s = sm + P_OFF;   // [128][PPAD]

    const int tid = threadIdx.x;
    const int cta = blockIdx.x;
    const int jc  = cta & 31;     // 32 j-chunks
    const int bc  = cta >> 5;     // 4 batch-chunks

    // ---- Prologue: build combined weight tile in SMEM (coalesced gmem reads)
    for (int idx = tid; idx < NROWS * H; idx += NTHREADS) {
        int rl = idx >> 9, k = idx & (H - 1);
        int g = rl >> 4, j = rl & 15;
        int grow = jc * JC + j;
        float v;
        if (g == 0)      v = W_ih[(size_t)grow * H + k]           + W_hh[(size_t)grow * H + k];
        else if (g == 1) v = W_ih[(size_t)(H + grow) * H + k]     + W_hh[(size_t)(H + grow) * H + k];
        else if (g == 2) v = W_ih[(size_t)(2*H + grow) * H + k];
        else             v = W_hh[(size_t)(2*H + grow) * H + k];
        w_s[rl * WPAD + k] = v;
    }
    if (tid < NROWS) {
        int g = tid >> 4, j = tid & 15;
        int grow = jc * JC + j;
        float v;
        if (g == 0)      v = b_ih[grow]        + b_hh[grow];
        else if (g == 1) v = b_ih[H + grow]    + b_hh[H + grow];
        else if (g == 2) v = b_ih[2*H + grow];
        else             v = b_hh[2*H + grow];
        bias_s[tid] = v;
    }
    __syncthreads();

    const int lj = tid & 15;          // j within chunk
    const int bg = (tid >> 4) & 7;    // batch group (4 rows each)
    const int kh = tid >> 7;          // k half: 0 -> [0,256), 1 -> [256,512)

    // Operand pointers are invariant across timesteps — hoist.
    // ulonglong2 view: one LDS.128 yields two packed f32x2 operands.
    const ulonglong2* W0 = (const ulonglong2*)(w_s + (0*JC + lj) * WPAD + kh * (H/2));
    const ulonglong2* W1 = (const ulonglong2*)(w_s + (1*JC + lj) * WPAD + kh * (H/2));
    const ulonglong2* W2 = (const ulonglong2*)(w_s + (2*JC + lj) * WPAD + kh * (H/2));
    const ulonglong2* W3 = (const ulonglong2*)(w_s + (3*JC + lj) * WPAD + kh * (H/2));
    const ulonglong2* Hv0 = (const ulonglong2*)(h_s + (bg*4 + 0) * H + kh * (H/2));
    const ulonglong2* Hv1 = (const ulonglong2*)(h_s + (bg*4 + 1) * H + kh * (H/2));
    const ulonglong2* Hv2 = (const ulonglong2*)(h_s + (bg*4 + 2) * H + kh * (H/2));
    const ulonglong2* Hv3 = (const ulonglong2*)(h_s + (bg*4 + 3) * H + kh * (H/2));

    const float bias0 = bias_s[0*JC + lj];
    const float bias1 = bias_s[1*JC + lj];
    const float bias2 = bias_s[2*JC + lj];
    const float bias3 = bias_s[3*JC + lj];

    for (int t = 1; t < TSTEPS; ++t) {
        // ---- load h tile (this CTA's 32 batch rows of out[t-1]) into SMEM
        const float4* src = (const float4*)(out + (size_t)(t - 1) * STEP_ELEMS
                                            + (size_t)bc * BC * H);
        float4* hdst = (float4*)h_s;
        #pragma unroll
        for (int i = 0; i < (BC * H / 4) / NTHREADS; ++i)
            hdst[tid + i * NTHREADS] = __ldcg(src + tid + i * NTHREADS);
        __syncthreads();

        // ---- 16 dot-products (4 gates x 4 batches), packed f32x2 over k
        u64 a0[4] = {0,0,0,0}, a1[4] = {0,0,0,0};
        u64 a2[4] = {0,0,0,0}, a3[4] = {0,0,0,0};

        #pragma unroll 8
        for (int kk = 0; kk < (H/2) / 4; ++kk) {
            ulonglong2 w0 = W0[kk], w1 = W1[kk], w2 = W2[kk], w3 = W3[kk];
            ulonglong2 x0 = Hv0[kk], x1 = Hv1[kk], x2 = Hv2[kk], x3 = Hv3[kk];
            FFMA2(a0[0], w0.x, x0.x); FFMA2(a0[0], w0.y, x0.y);
            FFMA2(a0[1], w0.x, x1.x); FFMA2(a0[1], w0.y, x1.y);
            FFMA2(a0[2], w0.x, x2.x); FFMA2(a0[2], w0.y, x2.y);
            FFMA2(a0[3], w0.x, x3.x); FFMA2(a0[3], w0.y, x3.y);
            FFMA2(a1[0], w1.x, x0.x); FFMA2(a1[0], w1.y, x0.y);
            FFMA2(a1[1], w1.x, x1.x); FFMA2(a1[1], w1.y, x1.y);
            FFMA2(a1[2], w1.x, x2.x); FFMA2(a1[2], w1.y, x2.y);
            FFMA2(a1[3], w1.x, x3.x); FFMA2(a1[3], w1.y, x3.y);
            FFMA2(a2[0], w2.x, x0.x); FFMA2(a2[0], w2.y, x0.y);
            FFMA2(a2[1], w2.x, x1.x); FFMA2(a2[1], w2.y, x1.y);
            FFMA2(a2[2], w2.x, x2.x); FFMA2(a2[2], w2.y, x2.y);
            FFMA2(a2[3], w2.x, x3.x); FFMA2(a2[3], w2.y, x3.y);
            FFMA2(a3[0], w3.x, x0.x); FFMA2(a3[0], w3.y, x0.y);
            FFMA2(a3[1], w3.x, x1.x); FFMA2(a3[1], w3.y, x1.y);
            FFMA2(a3[2], w3.x, x2.x); FFMA2(a3[2], w3.y, x2.y);
            FFMA2(a3[3], w3.x, x3.x); FFMA2(a3[3], w3.y, x3.y);
        }

        // Horizontal pair reduction -> scalar partials
        float s0[4], s1[4], s2[4], s3[4];
        #pragma unroll
        for (int i = 0; i < 4; ++i) {
            s0[i] = pairsum(a0[i]);
            s1[i] = pairsum(a1[i]);
            s2[i] = pairsum(a2[i]);
            s3[i] = pairsum(a3[i]);
        }

        // ---- cross-half reduction via SMEM (kh==1 -> kh==0)
        if (kh == 1) {
            float4* p = (float4*)(part_s + (tid & 127) * PPAD);
            p[0] = make_float4(s0[0], s0[1], s0[2], s0[3]);
            p[1] = make_float4(s1[0], s1[1], s1[2], s1[3]);
            p[2] = make_float4(s2[0], s2[1], s2[2], s2[3]);
            p[3] = make_float4(s3[0], s3[1], s3[2], s3[3]);
        }
        __syncthreads();

        if (kh == 0) {
            const float4* p = (const float4*)(part_s + tid * PPAD);
            float4 q0 = p[0], q1 = p[1], q2 = p[2], q3 = p[3];
            s0[0] += q0.x; s0[1] += q0.y; s0[2] += q0.z; s0[3] += q0.w;
            s1[0] += q1.x; s1[1] += q1.y; s1[2] += q1.z; s1[3] += q1.w;
            s2[0] += q2.x; s2[1] += q2.y; s2[2] += q2.z; s2[3] += q2.w;
            s3[0] += q3.x; s3[1] += q3.y; s3[2] += q3.z; s3[3] += q3.w;

            const int jglob = jc * JC + lj;
            float* dst = out + (size_t)t * STEP_ELEMS + (size_t)(bc * BC + bg * 4) * H + jglob;
            #pragma unroll
            for (int i = 0; i < 4; ++i) {
                float r = sigm(s0[i] + bias0);
                float z = sigm(s1[i] + bias1);
                float n = tanhf(s2[i] + bias2 + r * (s3[i] + bias3));
                float ho = h_s[(bg * 4 + i) * H + jglob];
                dst[(size_t)i * H] = n + z * (ho - n);   // (1-z)*n + z*h
            }
        }

        // ---- grid barrier (skip after final step)
        if (t + 1 < TSTEPS) {
            __threadfence();      // publish out[t] stores gpu-wide
            __syncthreads();
            if (tid == 0) {
                atomicAdd(&g_count, 1ULL);
                unsigned long long target = (unsigned long long)t * (unsigned long long)GRID;
                while (*(volatile unsigned long long*)&g_count < target) { }
            }
            __syncthreads();
        }
    }
}

// ---------------------------------------------------------------------------
// Harness entry
// Inputs (metadata order): encoder_outputs f32[1,128,100,512], W_ih f32[1536,512],
//   W_hh f32[1536,512], b_ih f32[1536], b_hh f32[1536], out_len i32 (unused; fixed 1024)
// Output: f32[1024*128, 1, 512]
// ---------------------------------------------------------------------------
extern "C" void kernel_launch(void* const* d_in, const int* in_sizes, int n_in,
                              void* d_out, int out_size)
{
    const float* enc  = (const float*)d_in[0];
    const float* W_ih = (const float*)d_in[1];
    const float* W_hh = (const float*)d_in[2];
    const float* b_ih = (const float*)d_in[3];
    const float* b_hh = (const float*)d_in[4];
    float* out = (float*)d_out;

    cudaFuncSetAttribute(gru_persist, cudaFuncAttributeMaxDynamicSharedMemorySize, SMEM_BYTES);

    init_kernel<<<1, 1>>>();
    gru_step0<<<BATCH, NTHREADS>>>(enc, W_hh, b_ih, b_hh, out);
    gru_persist<<<GRID, NTHREADS, SMEM_BYTES>>>(W_ih, W_hh, b_ih, b_hh, out);
}